// round 1
// baseline (speedup 1.0000x reference)
#include <cuda_runtime.h>
#include <math.h>

// Problem constants (fixed shapes per reference)
#define BB 8192
#define DD 128
#define RR 64
#define CC 64

// ---------------- device scratch (no allocations allowed) ----------------
__device__ float g_psum[64 * 128];      // BN partial sums  [block][d]
__device__ float g_psq [64 * 128];      // BN partial sumsq [block][d]
__device__ float g_sc  [128];           // per-d scale  (gamma * rstd)
__device__ float g_sh  [128];           // per-d shift  (beta - mean*scale)
__device__ float g_inv [128 * 64];      // 1/(2 s^2)  [d][r]
__device__ int   g_count[64];           // nonzero-frs rows per rule
__device__ int   g_rows [64 * 8192];    // row ids per rule
__device__ float g_fvals[64 * 8192];    // frs values per rule

// ---------------- k0: zero output + counters ----------------
__global__ void k0_zero(float4* out4) {
    int idx = blockIdx.x * blockDim.x + threadIdx.x;   // 512*256 = 131072 = 524288/4
    out4[idx] = make_float4(0.f, 0.f, 0.f, 0.f);
    if (idx < 64) g_count[idx] = 0;
}

// ---------------- k1: BN partial sums (deterministic slots) ----------------
__global__ void k1_bnpartial(const float* __restrict__ x) {
    int tid = threadIdx.x;                 // 256
    int blk = blockIdx.x;                  // 64 blocks, 128 rows each
    const float* xp = x + (size_t)blk * 128 * 128;
    float s = 0.f, s2 = 0.f;
    #pragma unroll 8
    for (int it = 0; it < 64; ++it) {
        float v = xp[it * 256 + tid];      // fully coalesced; d = tid&127 invariant
        s += v; s2 += v * v;
    }
    __shared__ float ps[256], ps2[256];
    ps[tid] = s; ps2[tid] = s2;
    __syncthreads();
    if (tid < 128) {
        g_psum[blk * 128 + tid] = ps[tid] + ps[tid + 128];
        g_psq [blk * 128 + tid] = ps2[tid] + ps2[tid + 128];
    }
}

// ---------------- k2: finalize BN + gaussian coefficients ----------------
__global__ void k2_finalize(const float* __restrict__ sigmas,
                            const float* __restrict__ gamma,
                            const float* __restrict__ beta) {
    int d = threadIdx.x;                   // 128
    float s = 0.f, s2 = 0.f;
    #pragma unroll 8
    for (int k = 0; k < 64; ++k) { s += g_psum[k * 128 + d]; s2 += g_psq[k * 128 + d]; }
    float mean = s  * (1.0f / 8192.0f);
    float var  = s2 * (1.0f / 8192.0f) - mean * mean;
    var = fmaxf(var, 0.0f);
    float sc = gamma[d] / sqrtf(var + 1e-5f);
    g_sc[d] = sc;
    g_sh[d] = beta[d] - mean * sc;
    #pragma unroll 4
    for (int r = 0; r < 64; ++r) {
        float sg = sigmas[d * 64 + r];
        g_inv[d * 64 + r] = 1.0f / (2.0f * sg * sg);
    }
}

// ---------------- k3: firing strengths + compacted per-rule lists ----------------
// 256 threads = 8 warps, each warp handles 4 rows; 256 blocks cover B=8192.
// smem: (center, inv2s2) pairs for all [128][64].
__global__ void k3_frs(const float* __restrict__ x,
                       const float* __restrict__ centers,
                       const float* __restrict__ rule_masks) {
    extern __shared__ float2 cs[];         // [128][64] = 64KB
    int tid = threadIdx.x;
    for (int k = tid; k < 128 * 64; k += 256)
        cs[k] = make_float2(centers[k], g_inv[k]);
    __syncthreads();

    int lane = tid & 31, wid = tid >> 5;
    float m0 = rule_masks[lane];
    float m1 = rule_masks[lane + 32];
    int rowbase = blockIdx.x * 32 + wid * 4;

    for (int rr = 0; rr < 4; ++rr) {
        int b = rowbase + rr;
        const float* xr = x + (size_t)b * 128;
        float xq[4];
        xq[0] = xr[lane]; xq[1] = xr[32 + lane]; xq[2] = xr[64 + lane]; xq[3] = xr[96 + lane];
        float acc0 = 0.f, acc1 = 0.f;
        #pragma unroll
        for (int j = 0; j < 4; ++j) {
            float xv = xq[j];
            #pragma unroll 8
            for (int t = 0; t < 32; ++t) {
                float xd = __shfl_sync(0xffffffffu, xv, t);
                int d = j * 32 + t;
                float2 c0 = cs[d * 64 + lane];
                float2 c1 = cs[d * 64 + 32 + lane];
                float df0 = xd - c0.x;
                float df1 = xd - c1.x;
                acc0 = fmaf(df0 * df0, c0.y, acc0);
                acc1 = fmaf(df1 * df1, c1.y, acc1);
            }
        }
        // logits = -acc (+ AMPLI=0); raw = exp(logit) * mask
        float raw0 = expf(-acc0) * m0;
        float raw1 = expf(-acc1) * m1;
        float ssum = raw0 + raw1;
        #pragma unroll
        for (int off = 16; off; off >>= 1)
            ssum += __shfl_xor_sync(0xffffffffu, ssum, off);
        float denom = ssum + 1e-10f;
        float frs0 = raw0 / denom;
        float frs1 = raw1 / denom;
        if (frs0 > 0.0f) {
            int p = atomicAdd(&g_count[lane], 1);
            g_rows [lane * 8192 + p] = b;
            g_fvals[lane * 8192 + p] = frs0;
        }
        if (frs1 > 0.0f) {
            int p = atomicAdd(&g_count[lane + 32], 1);
            g_rows [(lane + 32) * 8192 + p] = b;
            g_fvals[(lane + 32) * 8192 + p] = frs1;
        }
    }
}

// ---------------- k4: gathered per-rule GEMM ----------------
// grid (128 tiles, 64 rules), 256 threads. Tile: 64 gathered rows x 64 cols, K=128.
// out[b,c] += frs * (xn[b,:] . W[r,:,c] + bias[r,c])
__global__ void k4_out(const float* __restrict__ x,
                       const float* __restrict__ weights,
                       const float* __restrict__ biases,
                       float* __restrict__ out) {
    int r = blockIdx.y;
    int cnt = g_count[r];
    int base = blockIdx.x * 64;
    if (base >= cnt) return;
    int m = min(64, cnt - base);

    extern __shared__ float sm[];
    float* xsT = sm;            // [128][64]  (d-major, xn with frs-row gather)
    float* Ws  = sm + 8192;     // [128][64]
    __shared__ float frs_s[64], bias_s[64];
    __shared__ int   rows_s[64];

    int tid = threadIdx.x;
    if (tid < 64) {
        bias_s[tid] = biases[r * 64 + tid];
        if (tid < m) {
            rows_s[tid] = g_rows [r * 8192 + base + tid];
            frs_s[tid]  = g_fvals[r * 8192 + base + tid];
        } else {
            rows_s[tid] = 0;
            frs_s[tid]  = 0.f;
        }
    }
    __syncthreads();

    const float* Wg = weights + (size_t)r * 8192;   // [d][c] row-major
    for (int k = tid; k < 8192; k += 256) Ws[k] = Wg[k];
    for (int k = tid; k < 8192; k += 256) {
        int i = k & 63, d = k >> 6;                 // k = d*64 + i
        float v = 0.f;
        if (i < m) {
            int b = rows_s[i];
            v = x[(size_t)b * 128 + d] * g_sc[d] + g_sh[d];
        }
        xsT[k] = v;
    }
    __syncthreads();

    int tx = tid & 15, ty = tid >> 4;               // 16x16 threads, 4x4 register tile
    float acc[4][4] = {};
    #pragma unroll 4
    for (int d = 0; d < 128; ++d) {
        float4 a  = *(const float4*)(xsT + d * 64 + ty * 4);
        float4 bv = *(const float4*)(Ws  + d * 64 + tx * 4);
        acc[0][0] = fmaf(a.x, bv.x, acc[0][0]); acc[0][1] = fmaf(a.x, bv.y, acc[0][1]);
        acc[0][2] = fmaf(a.x, bv.z, acc[0][2]); acc[0][3] = fmaf(a.x, bv.w, acc[0][3]);
        acc[1][0] = fmaf(a.y, bv.x, acc[1][0]); acc[1][1] = fmaf(a.y, bv.y, acc[1][1]);
        acc[1][2] = fmaf(a.y, bv.z, acc[1][2]); acc[1][3] = fmaf(a.y, bv.w, acc[1][3]);
        acc[2][0] = fmaf(a.z, bv.x, acc[2][0]); acc[2][1] = fmaf(a.z, bv.y, acc[2][1]);
        acc[2][2] = fmaf(a.z, bv.z, acc[2][2]); acc[2][3] = fmaf(a.z, bv.w, acc[2][3]);
        acc[3][0] = fmaf(a.w, bv.x, acc[3][0]); acc[3][1] = fmaf(a.w, bv.y, acc[3][1]);
        acc[3][2] = fmaf(a.w, bv.z, acc[3][2]); acc[3][3] = fmaf(a.w, bv.w, acc[3][3]);
    }

    #pragma unroll
    for (int ii = 0; ii < 4; ++ii) {
        int i = ty * 4 + ii;
        if (i < m) {
            int b = rows_s[i];
            float f = frs_s[i];
            #pragma unroll
            for (int jj = 0; jj < 4; ++jj) {
                int c = tx * 4 + jj;
                atomicAdd(out + (size_t)b * 64 + c, f * (acc[ii][jj] + bias_s[c]));
            }
        }
    }
}

// ---------------- launch ----------------
extern "C" void kernel_launch(void* const* d_in, const int* in_sizes, int n_in,
                              void* d_out, int out_size) {
    const float* x       = (const float*)d_in[0];
    const float* centers = (const float*)d_in[1];
    const float* sigmas  = (const float*)d_in[2];
    const float* weights = (const float*)d_in[3];
    const float* biases  = (const float*)d_in[4];
    const float* gamma   = (const float*)d_in[5];
    const float* beta    = (const float*)d_in[6];
    const float* masks   = (const float*)d_in[7];
    float* out = (float*)d_out;

    cudaFuncSetAttribute(k3_frs, cudaFuncAttributeMaxDynamicSharedMemorySize, 65536);
    cudaFuncSetAttribute(k4_out, cudaFuncAttributeMaxDynamicSharedMemorySize, 65536);

    k0_zero<<<512, 256>>>((float4*)out);
    k1_bnpartial<<<64, 256>>>(x);
    k2_finalize<<<1, 128>>>(sigmas, gamma, beta);
    k3_frs<<<256, 256, 65536>>>(x, centers, masks);
    dim3 g4(128, 64);
    k4_out<<<g4, 256, 65536>>>(x, weights, biases, out);
}

// round 2
// speedup vs baseline: 1.4990x; 1.4990x over previous
#include <cuda_runtime.h>
#include <math.h>

// Shapes fixed per reference: B=8192, D=128, R=64, C=64
// Sparsity: logits ~ N(-170, 22); exp underflows to exactly 0 unless logit > -103.28,
// so only ~600 of 524288 (b,r) pairs have frs > 0. We compute frs exactly (same fp32
// formulation as reference), compact the nonzero pairs per rule, and run a tiny
// gathered GEMM only for those.

// ---------------- device scratch ----------------
__device__ float  g_psum[128 * 128];     // BN partial sums,  transposed: [d][blk]
__device__ float  g_psq [128 * 128];     // BN partial sumsq: [d][blk]
__device__ float2 g_scsh[128];           // per-d (scale, shift)
__device__ float4 g_coef[128 * 32];      // [d][lane] = (c_l, inv_l, c_{l+32}, inv_{l+32})
__device__ int    g_count[64];           // nonzero rows per rule
__device__ int    g_rows [64 * 8192];
__device__ float  g_fvals[64 * 8192];

// ---------------- kA: zero out + BN partials + coef pack + counter reset ----------------
// grid 128, block 256
__global__ void kA_prep(const float* __restrict__ x,
                        const float* __restrict__ centers,
                        const float* __restrict__ sigmas,
                        float4* __restrict__ out4) {
    int blk = blockIdx.x, tid = threadIdx.x;

    // zero output: 131072 float4 / 128 blocks = 1024 / block
    #pragma unroll
    for (int k = 0; k < 4; ++k)
        out4[blk * 1024 + k * 256 + tid] = make_float4(0.f, 0.f, 0.f, 0.f);

    // reset counters
    if (blk == 0 && tid < 64) g_count[tid] = 0;

    // pack gaussian coefficients: 4096 float4 total, 32 per block
    if (tid < 32) {
        int f = blk * 32 + tid;          // f = d*32 + lane
        int d = f >> 5, ln = f & 31;
        float s0 = sigmas[d * 64 + ln];
        float s1 = sigmas[d * 64 + ln + 32];
        g_coef[f] = make_float4(centers[d * 64 + ln],      1.0f / (2.0f * s0 * s0),
                                centers[d * 64 + ln + 32], 1.0f / (2.0f * s1 * s1));
    }

    // BN partial sums over rows [blk*64, blk*64+64)
    const float* xp = x + (size_t)blk * 64 * 128;
    float s = 0.f, s2 = 0.f;
    #pragma unroll 8
    for (int it = 0; it < 32; ++it) {
        float v = xp[it * 256 + tid];    // d = tid & 127, invariant over it
        s += v; s2 += v * v;
    }
    __shared__ float ps[256], ps2[256];
    ps[tid] = s; ps2[tid] = s2;
    __syncthreads();
    if (tid < 128) {
        g_psum[tid * 128 + blk] = ps[tid] + ps[tid + 128];   // transposed: [d][blk]
        g_psq [tid * 128 + blk] = ps2[tid] + ps2[tid + 128];
    }
}

// ---------------- kB: BN finalize ----------------
// 1 block, 1024 threads: 8 threads per d, each sums 16 partials.
__global__ void kB_finalize(const float* __restrict__ gamma,
                            const float* __restrict__ beta) {
    int tid = threadIdx.x;
    int d = tid >> 3, s8 = tid & 7;
    const float4* ps4  = (const float4*)(g_psum + d * 128) + s8 * 4;
    const float4* ps4b = (const float4*)(g_psq  + d * 128) + s8 * 4;
    float s = 0.f, s2 = 0.f;
    #pragma unroll
    for (int k = 0; k < 4; ++k) {
        float4 a = ps4[k];  s  += (a.x + a.y) + (a.z + a.w);
        float4 b = ps4b[k]; s2 += (b.x + b.y) + (b.z + b.w);
    }
    #pragma unroll
    for (int off = 4; off; off >>= 1) {
        s  += __shfl_down_sync(0xffffffffu, s,  off, 8);
        s2 += __shfl_down_sync(0xffffffffu, s2, off, 8);
    }
    if (s8 == 0) {
        float mean = s  * (1.0f / 8192.0f);
        float var  = s2 * (1.0f / 8192.0f) - mean * mean;
        var = fmaxf(var, 0.0f);
        float sc = gamma[d] / sqrtf(var + 1e-5f);
        g_scsh[d] = make_float2(sc, beta[d] - mean * sc);
    }
}

// ---------------- kC: firing strengths + per-rule compaction ----------------
// grid 444, block 256 (8 warps). smem: g_coef copy [d][lane] float4 = 64KB.
// Each warp iteration processes a PAIR of rows sharing coefficient loads.
// Lane l accumulates rules l and l+32 for both rows.
__global__ void kC_frs(const float* __restrict__ x,
                       const float* __restrict__ rule_masks) {
    extern __shared__ float4 cs4[];      // 4096 float4
    int tid = threadIdx.x;
    const float4* gc = g_coef;
    for (int k = tid; k < 4096; k += 256) cs4[k] = gc[k];
    __syncthreads();

    int lane = tid & 31, wid = tid >> 5;
    float m0 = rule_masks[lane];
    float m1 = rule_masks[lane + 32];
    int w = blockIdx.x * 8 + wid;        // global warp id, [0, 3552)

    for (int p = w; p < 4096; p += 3552) {
        int b0 = 2 * p, b1 = 2 * p + 1;
        const float* xr0 = x + (size_t)b0 * 128;
        const float* xr1 = x + (size_t)b1 * 128;
        float xq0[4], xq1[4];
        #pragma unroll
        for (int j = 0; j < 4; ++j) {
            xq0[j] = xr0[j * 32 + lane];
            xq1[j] = xr1[j * 32 + lane];
        }
        float a00 = 0.f, a01 = 0.f, a10 = 0.f, a11 = 0.f;
        #pragma unroll
        for (int j = 0; j < 4; ++j) {
            float xv0 = xq0[j], xv1 = xq1[j];
            #pragma unroll 8
            for (int t = 0; t < 32; ++t) {
                float xd0 = __shfl_sync(0xffffffffu, xv0, t);
                float xd1 = __shfl_sync(0xffffffffu, xv1, t);
                float4 cf = cs4[(j * 32 + t) * 32 + lane];
                float d00 = xd0 - cf.x;  a00 = fmaf(d00 * d00, cf.y, a00);
                float d01 = xd0 - cf.z;  a01 = fmaf(d01 * d01, cf.w, a01);
                float d10 = xd1 - cf.x;  a10 = fmaf(d10 * d10, cf.y, a10);
                float d11 = xd1 - cf.z;  a11 = fmaf(d11 * d11, cf.w, a11);
            }
        }
        float r00 = expf(-a00) * m0, r01 = expf(-a01) * m1;
        float r10 = expf(-a10) * m0, r11 = expf(-a11) * m1;
        float s0 = r00 + r01, s1 = r10 + r11;
        #pragma unroll
        for (int off = 16; off; off >>= 1) {
            s0 += __shfl_xor_sync(0xffffffffu, s0, off);
            s1 += __shfl_xor_sync(0xffffffffu, s1, off);
        }
        float inv0 = 1.0f, inv1 = 1.0f;  // compute frs exactly like reference: raw/denom
        inv0 = s0 + 1e-10f; inv1 = s1 + 1e-10f;
        float f00 = r00 / inv0, f01 = r01 / inv0;
        float f10 = r10 / inv1, f11 = r11 / inv1;
        if (f00 > 0.f) { int q = atomicAdd(&g_count[lane], 1);
                         g_rows[lane * 8192 + q] = b0; g_fvals[lane * 8192 + q] = f00; }
        if (f01 > 0.f) { int q = atomicAdd(&g_count[lane + 32], 1);
                         g_rows[(lane + 32) * 8192 + q] = b0; g_fvals[(lane + 32) * 8192 + q] = f01; }
        if (f10 > 0.f) { int q = atomicAdd(&g_count[lane], 1);
                         g_rows[lane * 8192 + q] = b1; g_fvals[lane * 8192 + q] = f10; }
        if (f11 > 0.f) { int q = atomicAdd(&g_count[lane + 32], 1);
                         g_rows[(lane + 32) * 8192 + q] = b1; g_fvals[(lane + 32) * 8192 + q] = f11; }
    }
}

// ---------------- kD: gathered per-rule GEMM ----------------
// grid (4, 64), block 256. W loaded to smem once per block; tile-stride over the
// rule's compacted row list. out[b,c] += frs * ((xn[b,:] . W[r,:,c]) + bias[r,c])
__global__ void kD_out(const float* __restrict__ x,
                       const float* __restrict__ weights,
                       const float* __restrict__ biases,
                       float* __restrict__ out) {
    int r = blockIdx.y;
    int cnt = g_count[r];
    if ((int)blockIdx.x * 64 >= cnt) return;

    extern __shared__ float sm[];
    float* Ws  = sm;            // [128][64]
    float* xsT = sm + 8192;     // [128][64] d-major gathered xn
    __shared__ float  frs_s[64], bias_s[64];
    __shared__ int    rows_s[64];
    __shared__ float2 scsh_s[128];

    int tid = threadIdx.x;
    const float* Wg = weights + (size_t)r * 8192;
    for (int k = tid; k < 8192; k += 256) Ws[k] = Wg[k];
    if (tid < 64)  bias_s[tid] = biases[r * 64 + tid];
    if (tid < 128) scsh_s[tid] = g_scsh[tid];

    for (int base = blockIdx.x * 64; base < cnt; base += 256) {
        int m = min(64, cnt - base);
        __syncthreads();
        if (tid < 64) {
            if (tid < m) {
                rows_s[tid] = g_rows [r * 8192 + base + tid];
                frs_s[tid]  = g_fvals[r * 8192 + base + tid];
            } else { rows_s[tid] = 0; frs_s[tid] = 0.f; }
        }
        __syncthreads();
        for (int k = tid; k < 8192; k += 256) {
            int i = k & 63, d = k >> 6;
            float v = 0.f;
            if (i < m) {
                int b = rows_s[i];
                float2 ss = scsh_s[d];
                v = x[(size_t)b * 128 + d] * ss.x + ss.y;
            }
            xsT[k] = v;
        }
        __syncthreads();

        int tx = tid & 15, ty = tid >> 4;
        float acc[4][4] = {};
        #pragma unroll 4
        for (int d = 0; d < 128; ++d) {
            float4 a  = *(const float4*)(xsT + d * 64 + ty * 4);
            float4 bv = *(const float4*)(Ws  + d * 64 + tx * 4);
            acc[0][0] = fmaf(a.x, bv.x, acc[0][0]); acc[0][1] = fmaf(a.x, bv.y, acc[0][1]);
            acc[0][2] = fmaf(a.x, bv.z, acc[0][2]); acc[0][3] = fmaf(a.x, bv.w, acc[0][3]);
            acc[1][0] = fmaf(a.y, bv.x, acc[1][0]); acc[1][1] = fmaf(a.y, bv.y, acc[1][1]);
            acc[1][2] = fmaf(a.y, bv.z, acc[1][2]); acc[1][3] = fmaf(a.y, bv.w, acc[1][3]);
            acc[2][0] = fmaf(a.z, bv.x, acc[2][0]); acc[2][1] = fmaf(a.z, bv.y, acc[2][1]);
            acc[2][2] = fmaf(a.z, bv.z, acc[2][2]); acc[2][3] = fmaf(a.z, bv.w, acc[2][3]);
            acc[3][0] = fmaf(a.w, bv.x, acc[3][0]); acc[3][1] = fmaf(a.w, bv.y, acc[3][1]);
            acc[3][2] = fmaf(a.w, bv.z, acc[3][2]); acc[3][3] = fmaf(a.w, bv.w, acc[3][3]);
        }
        #pragma unroll
        for (int ii = 0; ii < 4; ++ii) {
            int i = ty * 4 + ii;
            if (i < m) {
                int b = rows_s[i];
                float f = frs_s[i];
                #pragma unroll
                for (int jj = 0; jj < 4; ++jj) {
                    int c = tx * 4 + jj;
                    atomicAdd(out + (size_t)b * 64 + c, f * (acc[ii][jj] + bias_s[c]));
                }
            }
        }
    }
}

// ---------------- launch ----------------
extern "C" void kernel_launch(void* const* d_in, const int* in_sizes, int n_in,
                              void* d_out, int out_size) {
    const float* x       = (const float*)d_in[0];
    const float* centers = (const float*)d_in[1];
    const float* sigmas  = (const float*)d_in[2];
    const float* weights = (const float*)d_in[3];
    const float* biases  = (const float*)d_in[4];
    const float* gamma   = (const float*)d_in[5];
    const float* beta    = (const float*)d_in[6];
    const float* masks   = (const float*)d_in[7];
    float* out = (float*)d_out;

    cudaFuncSetAttribute(kC_frs, cudaFuncAttributeMaxDynamicSharedMemorySize, 65536);
    cudaFuncSetAttribute(kD_out, cudaFuncAttributeMaxDynamicSharedMemorySize, 65536);

    kA_prep<<<128, 256>>>(x, centers, sigmas, (float4*)out);
    kB_finalize<<<1, 1024>>>(gamma, beta);
    kC_frs<<<444, 256, 65536>>>(x, masks);
    dim3 g4(4, 64);
    kD_out<<<g4, 256, 65536>>>(x, weights, biases, out);
}

// round 3
// speedup vs baseline: 1.5515x; 1.0350x over previous
#include <cuda_runtime.h>
#include <math.h>

// Shapes fixed per reference: B=8192, D=128, R=64, C=64
// exp(logits) underflows to exact 0 for all but ~600 of 524288 (b,r) pairs.
// Compute frs exactly like the reference, compact nonzero pairs into a flat
// list, and run one small GEMV per active pair.

// ---------------- device scratch ----------------
__device__ float  g_psum[128 * 128];     // BN partial sums,  transposed: [d][blk]
__device__ float  g_psq [128 * 128];     // BN partial sumsq: [d][blk]
__device__ float2 g_scsh[128];           // per-d (scale, shift)
__device__ float4 g_coef[128 * 32];      // [d][lane] = (c_l, inv_l, c_{l+32}, inv_{l+32})
__device__ int    g_npairs;              // active (b,r) pair count
__device__ int    g_pbr[8192 * 64];      // packed (b<<6)|r
__device__ float  g_pf [8192 * 64];      // frs value

// ---------------- kA: zero out + BN partials + coef pack + counter reset ----------------
// grid 128, block 256
__global__ void kA_prep(const float* __restrict__ x,
                        const float* __restrict__ centers,
                        const float* __restrict__ sigmas,
                        float4* __restrict__ out4) {
    int blk = blockIdx.x, tid = threadIdx.x;

    // zero output: 131072 float4 / 128 blocks
    #pragma unroll
    for (int k = 0; k < 4; ++k)
        out4[blk * 1024 + k * 256 + tid] = make_float4(0.f, 0.f, 0.f, 0.f);

    if (blk == 0 && tid == 0) g_npairs = 0;

    // pack gaussian coefficients: 4096 float4 total, 32 per block
    if (tid < 32) {
        int f = blk * 32 + tid;          // f = d*32 + lane
        int d = f >> 5, ln = f & 31;
        float s0 = sigmas[d * 64 + ln];
        float s1 = sigmas[d * 64 + ln + 32];
        g_coef[f] = make_float4(centers[d * 64 + ln],      1.0f / (2.0f * s0 * s0),
                                centers[d * 64 + ln + 32], 1.0f / (2.0f * s1 * s1));
    }

    // BN partial sums over rows [blk*64, blk*64+64)
    const float* xp = x + (size_t)blk * 64 * 128;
    float s = 0.f, s2 = 0.f;
    #pragma unroll 8
    for (int it = 0; it < 32; ++it) {
        float v = xp[it * 256 + tid];    // d = tid & 127, invariant over it
        s += v; s2 += v * v;
    }
    __shared__ float ps[256], ps2[256];
    ps[tid] = s; ps2[tid] = s2;
    __syncthreads();
    if (tid < 128) {
        g_psum[tid * 128 + blk] = ps[tid] + ps[tid + 128];   // transposed: [d][blk]
        g_psq [tid * 128 + blk] = ps2[tid] + ps2[tid + 128];
    }
}

// ---------------- kC: firing strengths + flat compaction (+ BN finalize in block 0) ----------------
// grid 444, block 256 (8 warps). smem: coef copy [d][lane] float4 = 64KB.
__global__ void kC_frs(const float* __restrict__ x,
                       const float* __restrict__ rule_masks,
                       const float* __restrict__ gamma,
                       const float* __restrict__ beta) {
    extern __shared__ float4 cs4[];      // 4096 float4
    int tid = threadIdx.x;

    // Block 0 additionally finalizes BN stats (consumed only by kD, which
    // launches strictly after this kernel completes).
    if (blockIdx.x == 0) {
        int d = tid >> 1, half = tid & 1;     // 2 threads per d
        const float* ps = g_psum + d * 128 + half * 64;
        const float* pq = g_psq  + d * 128 + half * 64;
        float s = 0.f, s2 = 0.f;
        #pragma unroll 8
        for (int k = 0; k < 64; ++k) { s += ps[k]; s2 += pq[k]; }
        s  += __shfl_xor_sync(0xffffffffu, s,  1);
        s2 += __shfl_xor_sync(0xffffffffu, s2, 1);
        if (half == 0) {
            float mean = s  * (1.0f / 8192.0f);
            float var  = s2 * (1.0f / 8192.0f) - mean * mean;
            var = fmaxf(var, 0.0f);
            float sc = gamma[d] / sqrtf(var + 1e-5f);
            g_scsh[d] = make_float2(sc, beta[d] - mean * sc);
        }
    }

    const float4* gc = g_coef;
    for (int k = tid; k < 4096; k += 256) cs4[k] = gc[k];
    __syncthreads();

    int lane = tid & 31, wid = tid >> 5;
    float m0 = rule_masks[lane];
    float m1 = rule_masks[lane + 32];
    int w = blockIdx.x * 8 + wid;        // global warp id, [0, 3552)

    for (int p = w; p < 4096; p += 3552) {
        int b0 = 2 * p, b1 = 2 * p + 1;
        const float* xr0 = x + (size_t)b0 * 128;
        const float* xr1 = x + (size_t)b1 * 128;
        float xq0[4], xq1[4];
        #pragma unroll
        for (int j = 0; j < 4; ++j) {
            xq0[j] = xr0[j * 32 + lane];
            xq1[j] = xr1[j * 32 + lane];
        }
        float a00 = 0.f, a01 = 0.f, a10 = 0.f, a11 = 0.f;
        #pragma unroll
        for (int j = 0; j < 4; ++j) {
            float xv0 = xq0[j], xv1 = xq1[j];
            #pragma unroll 8
            for (int t = 0; t < 32; ++t) {
                float xd0 = __shfl_sync(0xffffffffu, xv0, t);
                float xd1 = __shfl_sync(0xffffffffu, xv1, t);
                float4 cf = cs4[(j * 32 + t) * 32 + lane];
                float d00 = xd0 - cf.x;  a00 = fmaf(d00 * d00, cf.y, a00);
                float d01 = xd0 - cf.z;  a01 = fmaf(d01 * d01, cf.w, a01);
                float d10 = xd1 - cf.x;  a10 = fmaf(d10 * d10, cf.y, a10);
                float d11 = xd1 - cf.z;  a11 = fmaf(d11 * d11, cf.w, a11);
            }
        }
        float r00 = expf(-a00) * m0, r01 = expf(-a01) * m1;
        float r10 = expf(-a10) * m0, r11 = expf(-a11) * m1;
        float s0 = r00 + r01, s1 = r10 + r11;
        #pragma unroll
        for (int off = 16; off; off >>= 1) {
            s0 += __shfl_xor_sync(0xffffffffu, s0, off);
            s1 += __shfl_xor_sync(0xffffffffu, s1, off);
        }
        float den0 = s0 + 1e-10f, den1 = s1 + 1e-10f;
        float f00 = r00 / den0, f01 = r01 / den0;
        float f10 = r10 / den1, f11 = r11 / den1;
        if (f00 > 0.f) { int q = atomicAdd(&g_npairs, 1);
                         g_pbr[q] = (b0 << 6) | lane;        g_pf[q] = f00; }
        if (f01 > 0.f) { int q = atomicAdd(&g_npairs, 1);
                         g_pbr[q] = (b0 << 6) | (lane + 32); g_pf[q] = f01; }
        if (f10 > 0.f) { int q = atomicAdd(&g_npairs, 1);
                         g_pbr[q] = (b1 << 6) | lane;        g_pf[q] = f10; }
        if (f11 > 0.f) { int q = atomicAdd(&g_npairs, 1);
                         g_pbr[q] = (b1 << 6) | (lane + 32); g_pf[q] = f11; }
    }
}

// ---------------- kD: per-pair GEMV ----------------
// grid-stride over the flat pair list; 256 threads = 64 cols x 4 K-quarters.
// out[b,c] += frs * (xn[b,:] . W[r,:,c] + bias[r,c])
__global__ void kD_out(const float* __restrict__ x,
                       const float* __restrict__ weights,
                       const float* __restrict__ biases,
                       float* __restrict__ out) {
    __shared__ float  xn[128];
    __shared__ float  part[256];
    __shared__ float2 scsh[128];
    int tid = threadIdx.x;
    if (tid < 128) scsh[tid] = g_scsh[tid];
    int np = g_npairs;

    int c = tid & 63, kq = tid >> 6;
    for (int i = blockIdx.x; i < np; i += gridDim.x) {
        int packed = g_pbr[i];
        int b = packed >> 6, r = packed & 63;
        float f = g_pf[i];
        __syncthreads();
        if (tid < 128) {
            float2 ss = scsh[tid];
            xn[tid] = x[(size_t)b * 128 + tid] * ss.x + ss.y;
        }
        __syncthreads();
        const float* Wp = weights + (size_t)r * 8192 + (kq * 32) * 64 + c;
        const float* xq = xn + kq * 32;
        float acc = 0.f;
        #pragma unroll 8
        for (int j = 0; j < 32; ++j)
            acc = fmaf(xq[j], Wp[j * 64], acc);
        part[tid] = acc;
        __syncthreads();
        if (tid < 64) {
            float v = (part[tid] + part[tid + 64]) + (part[tid + 128] + part[tid + 192]);
            atomicAdd(out + (size_t)b * 64 + tid, f * (v + biases[r * 64 + tid]));
        }
    }
}

// ---------------- launch ----------------
extern "C" void kernel_launch(void* const* d_in, const int* in_sizes, int n_in,
                              void* d_out, int out_size) {
    const float* x       = (const float*)d_in[0];
    const float* centers = (const float*)d_in[1];
    const float* sigmas  = (const float*)d_in[2];
    const float* weights = (const float*)d_in[3];
    const float* biases  = (const float*)d_in[4];
    const float* gamma   = (const float*)d_in[5];
    const float* beta    = (const float*)d_in[6];
    const float* masks   = (const float*)d_in[7];
    float* out = (float*)d_out;

    cudaFuncSetAttribute(kC_frs, cudaFuncAttributeMaxDynamicSharedMemorySize, 65536);

    kA_prep<<<128, 256>>>(x, centers, sigmas, (float4*)out);
    kC_frs<<<444, 256, 65536>>>(x, masks, gamma, beta);
    kD_out<<<1024, 256>>>(x, weights, biases, out);
}